// round 15
// baseline (speedup 1.0000x reference)
#include <cuda_runtime.h>
#include <math.h>
#include <stdint.h>

// Problem constants: T=4, B=8, N=1024, C=512, NH=8, D=64, TB=32, M=TB*N=32768
#define MM 32768
#define O3 1536
#define CC 512

// ---------------- scratch (static __device__, no allocation) ----------------
__device__ float g_Y [(size_t)O3 * MM];   // qkv pre-activations   [o][m]
__device__ float g_Sa[(size_t)CC * MM];   // attention spikes      [c][m]
__device__ float g_P [(size_t)CC * MM];   // proj pre-activations  [c][m]
__device__ float g_scale [O3], g_shift [O3];
__device__ float g_scale2[CC], g_shift2[CC];
__device__ double g_part[2048][8][2];     // BN partial sums
__device__ uint32_t g_M[(size_t)O3 * 1024]; // spike bitmasks [ch][tb][32 words of n]
__device__ int g_KVi[256 * 4096];           // kv ints [g][d][e], g = tb*8+h

// ---------------- GEMM1 (R9/R14 bit-proven, unchanged) ----------------------
__global__ __launch_bounds__(256) void gemm_qkv(
    const float* __restrict__ Wq, const float* __restrict__ Wk,
    const float* __restrict__ Wv, const float* __restrict__ X)
{
    __shared__ float As[16][132];
    __shared__ float Bs[16][132];
    int m0 = blockIdx.x * 128;
    int o0 = blockIdx.y * 128;
    const float* W = Wq; int ob = o0;
    if (o0 >= 1024)      { W = Wv; ob = o0 - 1024; }
    else if (o0 >= 512)  { W = Wk; ob = o0 - 512;  }

    int tid = threadIdx.x;
    int tx = tid & 15, ty = tid >> 4;
    int lr = tid >> 2;
    int lk = (tid & 3) << 2;

    float acc[8][8];
#pragma unroll
    for (int i = 0; i < 8; i++)
#pragma unroll
        for (int j = 0; j < 8; j++) acc[i][j] = 0.f;

    for (int k0 = 0; k0 < 512; k0 += 16) {
#pragma unroll
        for (int rr = 0; rr < 2; rr++) {
            int r = lr + rr * 64;
            float4 a = *(const float4*)&W[(size_t)(ob + r) * 512 + k0 + lk];
            As[lk+0][r] = a.x; As[lk+1][r] = a.y; As[lk+2][r] = a.z; As[lk+3][r] = a.w;
            float4 b = *(const float4*)&X[(size_t)(m0 + r) * 512 + k0 + lk];
            Bs[lk+0][r] = b.x; Bs[lk+1][r] = b.y; Bs[lk+2][r] = b.z; Bs[lk+3][r] = b.w;
        }
        __syncthreads();
#pragma unroll
        for (int kk = 0; kk < 16; kk++) {
            float ar[8], br[8];
            *(float4*)&ar[0] = *(const float4*)&As[kk][ty*8];
            *(float4*)&ar[4] = *(const float4*)&As[kk][ty*8+4];
            *(float4*)&br[0] = *(const float4*)&Bs[kk][tx*8];
            *(float4*)&br[4] = *(const float4*)&Bs[kk][tx*8+4];
#pragma unroll
            for (int i = 0; i < 8; i++)
#pragma unroll
                for (int j = 0; j < 8; j++)
                    acc[i][j] = fmaf(ar[i], br[j], acc[i][j]);
        }
        __syncthreads();
    }
#pragma unroll
    for (int i = 0; i < 8; i++) {
        size_t row = (size_t)(o0 + ty*8 + i) * MM + m0 + tx*8;
        *(float4*)&g_Y[row]   = make_float4(acc[i][0], acc[i][1], acc[i][2], acc[i][3]);
        *(float4*)&g_Y[row+4] = make_float4(acc[i][4], acc[i][5], acc[i][6], acc[i][7]);
    }
}

// ---------------- GEMM2 (R9/R14 bit-proven, unchanged) ----------------------
__global__ __launch_bounds__(256) void gemm_proj(const float* __restrict__ W)
{
    __shared__ float As[16][132];
    __shared__ float Bs[16][132];
    int m0 = blockIdx.x * 128;
    int o0 = blockIdx.y * 128;
    int tid = threadIdx.x;
    int tx = tid & 15, ty = tid >> 4;
    int lr = tid >> 2;
    int lk = (tid & 3) << 2;
    int lc = tid >> 5;
    int lm = (tid & 31) << 2;

    float acc[8][8];
#pragma unroll
    for (int i = 0; i < 8; i++)
#pragma unroll
        for (int j = 0; j < 8; j++) acc[i][j] = 0.f;

    for (int k0 = 0; k0 < 512; k0 += 16) {
#pragma unroll
        for (int rr = 0; rr < 2; rr++) {
            int r = lr + rr * 64;
            float4 a = *(const float4*)&W[(size_t)(o0 + r) * 512 + k0 + lk];
            As[lk+0][r] = a.x; As[lk+1][r] = a.y; As[lk+2][r] = a.z; As[lk+3][r] = a.w;
        }
#pragma unroll
        for (int rr = 0; rr < 2; rr++) {
            int c = lc + rr * 8;
            float4 b = *(const float4*)&g_Sa[(size_t)(k0 + c) * MM + m0 + lm];
            *(float4*)&Bs[c][lm] = b;
        }
        __syncthreads();
#pragma unroll
        for (int kk = 0; kk < 16; kk++) {
            float ar[8], br[8];
            *(float4*)&ar[0] = *(const float4*)&As[kk][ty*8];
            *(float4*)&ar[4] = *(const float4*)&As[kk][ty*8+4];
            *(float4*)&br[0] = *(const float4*)&Bs[kk][tx*8];
            *(float4*)&br[4] = *(const float4*)&Bs[kk][tx*8+4];
#pragma unroll
            for (int i = 0; i < 8; i++)
#pragma unroll
                for (int j = 0; j < 8; j++)
                    acc[i][j] = fmaf(ar[i], br[j], acc[i][j]);
        }
        __syncthreads();
    }
#pragma unroll
    for (int i = 0; i < 8; i++) {
        size_t row = (size_t)(o0 + ty*8 + i) * MM + m0 + tx*8;
        *(float4*)&g_P[row]   = make_float4(acc[i][0], acc[i][1], acc[i][2], acc[i][3]);
        *(float4*)&g_P[row+4] = make_float4(acc[i][4], acc[i][5], acc[i][6], acc[i][7]);
    }
}

// -------- Neumaier compensated fp32 helpers (R14-proven) ----------------------
__device__ __forceinline__ void neum_add(float& s, float& c, float x) {
    float t = s + x;
    float e = (fabsf(s) >= fabsf(x)) ? ((s - t) + x) : ((x - t) + s);
    c += e; s = t;
}
__device__ __forceinline__ void neum_merge(float& s, float& c, float s2, float c2) {
    float t = s + s2;
    float e = (fabsf(s) >= fabsf(s2)) ? ((s - t) + s2) : ((s2 - t) + s);
    c = c + c2 + e; s = t;
}

__global__ __launch_bounds__(256) void bn_part(int which, int chbase)
{
    const float* Y = which ? g_P : g_Y;
    int c  = blockIdx.x;
    int sp = blockIdx.y;
    const float* p = Y + (size_t)c * MM + sp * 4096;
    int t = threadIdx.x;
    float s = 0.f, cs = 0.f, ss = 0.f, css = 0.f;
#pragma unroll
    for (int i = 0; i < 4; i++) {
        float4 v = *(const float4*)&p[i*1024 + t*4];
        neum_add(s, cs, v.x); neum_add(ss, css, v.x * v.x);
        neum_add(s, cs, v.y); neum_add(ss, css, v.y * v.y);
        neum_add(s, cs, v.z); neum_add(ss, css, v.z * v.z);
        neum_add(s, cs, v.w); neum_add(ss, css, v.w * v.w);
    }
#pragma unroll
    for (int o = 16; o > 0; o >>= 1) {
        float s2  = __shfl_down_sync(0xffffffffu, s,  o);
        float c2  = __shfl_down_sync(0xffffffffu, cs, o);
        neum_merge(s, cs, s2, c2);
        float t2  = __shfl_down_sync(0xffffffffu, ss,  o);
        float d2  = __shfl_down_sync(0xffffffffu, css, o);
        neum_merge(ss, css, t2, d2);
    }
    __shared__ float sh[8][4];
    int w = t >> 5;
    if ((t & 31) == 0) { sh[w][0] = s; sh[w][1] = cs; sh[w][2] = ss; sh[w][3] = css; }
    __syncthreads();
    if (t == 0) {
        double S = 0.0, SS = 0.0;
#pragma unroll
        for (int i = 0; i < 8; i++) {
            S  += (double)sh[i][0] + (double)sh[i][1];
            SS += (double)sh[i][2] + (double)sh[i][3];
        }
        g_part[chbase + c][sp][0] = S;
        g_part[chbase + c][sp][1] = SS;
    }
}

__global__ __launch_bounds__(256) void bn_final(int partbase, int outbase, int which,
    const float* __restrict__ gamma, const float* __restrict__ beta)
{
    int c = blockIdx.x * 256 + threadIdx.x;
    double s = 0.0, ss = 0.0;
#pragma unroll
    for (int i = 0; i < 8; i++) {
        s  += g_part[partbase + c][i][0];
        ss += g_part[partbase + c][i][1];
    }
    double mean = s * (1.0 / (double)MM);
    double var  = ss * (1.0 / (double)MM) - mean * mean;
    double inv  = 1.0 / sqrt(var + 1e-5);
    double g    = (double)gamma[c];
    float* sc = which ? g_scale2 : g_scale;
    float* sf = which ? g_shift2 : g_shift;
    sc[outbase + c] = (float)(g * inv);
    sf[outbase + c] = (float)((double)beta[c] - mean * g * inv);
}

// -------- LIF qkv + ballot pack: g_Y -> spike bitmasks (no float spikes) ------
__global__ __launch_bounds__(256) void lif_qkv_pack()
{
    int ch = blockIdx.x;            // 0..1535
    int b  = blockIdx.y;            // 0..7
    float sc = g_scale[ch], sf = g_shift[ch];
    int tid = threadIdx.x;
    int lane = tid & 31, wrp = tid >> 5;
#pragma unroll
    for (int iter = 0; iter < 4; iter++) {
        int n = iter * 256 + tid;
        float v = 0.f;
#pragma unroll
        for (int t = 0; t < 4; t++) {
            float xv = g_Y[(size_t)ch * MM + (size_t)t * 8192 + b * 1024 + n] * sc + sf;
            v = v + (xv - v) * 0.5f;
            bool s = (v >= 1.0f);
            uint32_t bal = __ballot_sync(0xffffffffu, s);
            if (lane == 0)
                g_M[(size_t)ch * 1024 + (t * 8 + b) * 32 + iter * 8 + wrp] = bal;
            if (s) v = 0.f;
        }
    }
}

// -------- kv ints: kv[g][d][e] = popc sums (exact) ----------------------------
__global__ __launch_bounds__(256) void kv_int()
{
    __shared__ uint32_t Ks[64][33];
    __shared__ uint32_t Vs[64][33];
    int g = blockIdx.x;             // tb*8 + h
    int tb = g >> 3, h = g & 7;
    int tid = threadIdx.x;
    for (int i = tid; i < 2048; i += 256) {
        int d = i >> 5, w = i & 31;
        Ks[d][w] = g_M[(size_t)(512  + h * 64 + d) * 1024 + tb * 32 + w];
        Vs[d][w] = g_M[(size_t)(1024 + h * 64 + d) * 1024 + tb * 32 + w];
    }
    __syncthreads();
    int d  = tid >> 2;
    int e0 = (tid & 3) << 4;
    int acc[16];
#pragma unroll
    for (int j = 0; j < 16; j++) acc[j] = 0;
#pragma unroll 4
    for (int w = 0; w < 32; w++) {
        uint32_t kw = Ks[d][w];
#pragma unroll
        for (int j = 0; j < 16; j++)
            acc[j] += __popc(kw & Vs[e0 + j][w]);
    }
#pragma unroll
    for (int j = 0; j < 16; j++)
        g_KVi[g * 4096 + d * 64 + e0 + j] = acc[j];
}

// -------- fused attn: a = q-mask · kv (int, exact) -> attn LIF -> g_Sa --------
__global__ __launch_bounds__(256) void attn_fused()
{
    __shared__ short    kvs[4][64][66];
    __shared__ uint32_t qs [4][64][2];
    int nt = blockIdx.x;            // 0..15 (n-tile of 64)
    int bh = blockIdx.y;            // 0..63
    int b = bh >> 3, h = bh & 7;
    int tid = threadIdx.x;
    int n = tid & 63;               // warp = 32 consecutive n
    int part = tid >> 6;            // 0..3 -> e range part*16..+15
    int e0 = part << 4;

    for (int i = tid; i < 16384; i += 256) {
        int t = i >> 12, r = i & 4095;
        int d = r >> 6, e = r & 63;
        kvs[t][d][e] = (short)g_KVi[(((t * 8 + b) * 8 + h)) * 4096 + d * 64 + e];
    }
    for (int i = tid; i < 512; i += 256) {
        int t = i >> 7, d = (i >> 1) & 63, nw = i & 1;
        qs[t][d][nw] = g_M[(size_t)(h * 64 + d) * 1024 + (t * 8 + b) * 32 + nt * 2 + nw];
    }
    __syncthreads();

    int nw = n >> 5, nb = n & 31;
    int acc[4][16];
#pragma unroll
    for (int t = 0; t < 4; t++)
#pragma unroll
        for (int j = 0; j < 16; j++) acc[t][j] = 0;

#pragma unroll 1
    for (int t = 0; t < 4; t++) {
#pragma unroll 1
        for (int d = 0; d < 64; d++) {
            if ((qs[t][d][nw] >> nb) & 1) {
                const uint32_t* kr = (const uint32_t*)&kvs[t][d][e0];
#pragma unroll
                for (int u = 0; u < 8; u++) {
                    uint32_t p = kr[u];
                    acc[t][2*u]   += (int)(p & 0xffffu);
                    acc[t][2*u+1] += (int)(p >> 16);
                }
            }
        }
    }

    // attn LIF (vth=0.5) over t, write float spikes for proj
#pragma unroll
    for (int j = 0; j < 16; j++) {
        int c = h * 64 + e0 + j;
        float v = 0.f;
#pragma unroll
        for (int t = 0; t < 4; t++) {
            float xv = (float)acc[t][j] * 0.125f;
            v = v + (xv - v) * 0.5f;
            bool s = (v >= 0.5f);
            g_Sa[(size_t)c * MM + (size_t)(t * 8 + b) * 1024 + nt * 64 + n] = s ? 1.f : 0.f;
            if (s) v = 0.f;
        }
    }
}

// -------- final LIF (vth=1.0, float4) + transpose to [T,B,C,H,W] --------------
__global__ __launch_bounds__(256) void lif_final(float* __restrict__ out)
{
    int c = blockIdx.x;
    int b = blockIdx.y;
    float sc = g_scale2[c], sf = g_shift2[c];
    int n4 = threadIdx.x * 4;
    float4 v = make_float4(0.f, 0.f, 0.f, 0.f);
#pragma unroll
    for (int t = 0; t < 4; t++) {
        float4 y = *(const float4*)&g_P[(size_t)c * MM + (size_t)(t*8 + b) * 1024 + n4];
        float4 xv = make_float4(y.x*sc+sf, y.y*sc+sf, y.z*sc+sf, y.w*sc+sf);
        v.x = v.x + (xv.x - v.x)*0.5f; v.y = v.y + (xv.y - v.y)*0.5f;
        v.z = v.z + (xv.z - v.z)*0.5f; v.w = v.w + (xv.w - v.w)*0.5f;
        bool s0 = v.x >= 1.0f, s1 = v.y >= 1.0f, s2 = v.z >= 1.0f, s3 = v.w >= 1.0f;
        *(float4*)&out[((size_t)(t*8 + b) * 512 + c) * 1024 + n4] =
            make_float4(s0?1.f:0.f, s1?1.f:0.f, s2?1.f:0.f, s3?1.f:0.f);
        if (s0) v.x = 0.f; if (s1) v.y = 0.f; if (s2) v.z = 0.f; if (s3) v.w = 0.f;
    }
}

// ---------------------------------------------------------------------------
extern "C" void kernel_launch(void* const* d_in, const int* in_sizes, int n_in,
                              void* d_out, int out_size)
{
    const float* x   = (const float*)d_in[0];
    const float* q_w = (const float*)d_in[1];
    const float* q_g = (const float*)d_in[2];
    const float* q_b = (const float*)d_in[3];
    const float* k_w = (const float*)d_in[4];
    const float* k_g = (const float*)d_in[5];
    const float* k_b = (const float*)d_in[6];
    const float* v_w = (const float*)d_in[7];
    const float* v_g = (const float*)d_in[8];
    const float* v_b = (const float*)d_in[9];
    const float* p_w = (const float*)d_in[10];
    // d_in[11] = proj_b: added before training-mode BN -> cancels exactly.
    const float* p_g = (const float*)d_in[12];
    const float* p_b = (const float*)d_in[13];
    float* out = (float*)d_out;

    // 1) fused QKV GEMM (bit-exact)
    gemm_qkv<<<dim3(MM/128, O3/128), 256>>>(q_w, k_w, v_w, x);
    // 2) BN stats (Neumaier fp32, stat-exact class)
    bn_part<<<dim3(O3, 8), 256>>>(0, 0);
    bn_final<<<2, 256>>>(0,    0,    0, q_g, q_b);
    bn_final<<<2, 256>>>(512,  512,  0, k_g, k_b);
    bn_final<<<2, 256>>>(1024, 1024, 0, v_g, v_b);
    // 3) LIF -> spike BITMASKS (exact)
    lif_qkv_pack<<<dim3(O3, 8), 256>>>();
    // 4) kv = popcount(K & V) per (t,b,h) — exact integers
    kv_int<<<256, 256>>>();
    // 5+6) a = q·kv (int, exact) + attn LIF fused -> float spikes
    attn_fused<<<dim3(16, 64), 256>>>();
    // 7) proj GEMM (bit-exact)
    gemm_proj<<<dim3(MM/128, CC/128), 256>>>(p_w);
    // 8) proj BN stats
    bn_part<<<dim3(CC, 8), 256>>>(1, 1536);
    bn_final<<<2, 256>>>(1536, 0, 1, p_g, p_b);
    // 9) final LIF (float4) + transpose
    lif_final<<<dim3(CC, 8), 256>>>(out);
}

// round 16
// speedup vs baseline: 1.2000x; 1.2000x over previous
#include <cuda_runtime.h>
#include <math.h>
#include <stdint.h>

// Problem constants: T=4, B=8, N=1024, C=512, NH=8, D=64, TB=32, M=TB*N=32768
#define MM 32768
#define O3 1536
#define CC 512

// ---------------- scratch (static __device__, no allocation) ----------------
__device__ float g_Y [(size_t)O3 * MM];   // qkv pre-activations   [o][m]
__device__ float g_S [(size_t)O3 * MM];   // qkv spikes            [o][m]
__device__ float g_KV[256 * 64 * 64];     // kv per (t,b,h)        [g][d][e]
__device__ float g_A [(size_t)CC * MM];   // attention pre-LIF     [c][m]
__device__ float g_Sa[(size_t)CC * MM];   // attention spikes      [c][m]
__device__ float g_P [(size_t)CC * MM];   // proj pre-activations  [c][m]
__device__ float g_scale [O3], g_shift [O3];
__device__ float g_scale2[CC], g_shift2[CC];
__device__ double g_accS [2048];          // fused BN sums   (qkv 0..1535, proj 1536..2047)
__device__ double g_accSS[2048];          // fused BN sumsqs

__global__ void zero_acc()
{
    int i = threadIdx.x;
    for (; i < 2048; i += 256) { g_accS[i] = 0.0; g_accSS[i] = 0.0; }
}

// -------- fused BN-partial epilogue helper (called with accs in registers) ----
__device__ __forceinline__ void bn_fused_epilogue(
    float acc[8][8], int lane, int ty, int obase)
{
#pragma unroll
    for (int i = 0; i < 8; i++) {
        float s = 0.f, ss = 0.f;
#pragma unroll
        for (int j = 0; j < 8; j++) {
            s += acc[i][j];
            ss = fmaf(acc[i][j], acc[i][j], ss);
        }
#pragma unroll
        for (int off = 8; off > 0; off >>= 1) {
            s  += __shfl_down_sync(0xffffffffu, s,  off, 16);
            ss += __shfl_down_sync(0xffffffffu, ss, off, 16);
        }
        if ((lane & 15) == 0) {
            atomicAdd(&g_accS [obase + ty * 8 + i], (double)s);
            atomicAdd(&g_accSS[obase + ty * 8 + i], (double)ss);
        }
    }
}

// ---------------- GEMM1: g_Y[o][m] = sum_c W[o][c] * X[m][c] ----------------
// Bit-exact vs reference; now also accumulates BN stats from registers.
__global__ __launch_bounds__(256) void gemm_qkv(
    const float* __restrict__ Wq, const float* __restrict__ Wk,
    const float* __restrict__ Wv, const float* __restrict__ X)
{
    __shared__ float As[16][132];
    __shared__ float Bs[16][132];
    int m0 = blockIdx.x * 128;
    int o0 = blockIdx.y * 128;
    const float* W = Wq; int ob = o0;
    if (o0 >= 1024)      { W = Wv; ob = o0 - 1024; }
    else if (o0 >= 512)  { W = Wk; ob = o0 - 512;  }

    int tid = threadIdx.x;
    int tx = tid & 15, ty = tid >> 4;
    int lr = tid >> 2;            // 0..63
    int lk = (tid & 3) << 2;      // 0,4,8,12

    float acc[8][8];
#pragma unroll
    for (int i = 0; i < 8; i++)
#pragma unroll
        for (int j = 0; j < 8; j++) acc[i][j] = 0.f;

    for (int k0 = 0; k0 < 512; k0 += 16) {
#pragma unroll
        for (int rr = 0; rr < 2; rr++) {
            int r = lr + rr * 64;
            float4 a = *(const float4*)&W[(size_t)(ob + r) * 512 + k0 + lk];
            As[lk+0][r] = a.x; As[lk+1][r] = a.y; As[lk+2][r] = a.z; As[lk+3][r] = a.w;
            float4 b = *(const float4*)&X[(size_t)(m0 + r) * 512 + k0 + lk];
            Bs[lk+0][r] = b.x; Bs[lk+1][r] = b.y; Bs[lk+2][r] = b.z; Bs[lk+3][r] = b.w;
        }
        __syncthreads();
#pragma unroll
        for (int kk = 0; kk < 16; kk++) {
            float ar[8], br[8];
            *(float4*)&ar[0] = *(const float4*)&As[kk][ty*8];
            *(float4*)&ar[4] = *(const float4*)&As[kk][ty*8+4];
            *(float4*)&br[0] = *(const float4*)&Bs[kk][tx*8];
            *(float4*)&br[4] = *(const float4*)&Bs[kk][tx*8+4];
#pragma unroll
            for (int i = 0; i < 8; i++)
#pragma unroll
                for (int j = 0; j < 8; j++)
                    acc[i][j] = fmaf(ar[i], br[j], acc[i][j]);
        }
        __syncthreads();
    }
#pragma unroll
    for (int i = 0; i < 8; i++) {
        size_t row = (size_t)(o0 + ty*8 + i) * MM + m0 + tx*8;
        *(float4*)&g_Y[row]   = make_float4(acc[i][0], acc[i][1], acc[i][2], acc[i][3]);
        *(float4*)&g_Y[row+4] = make_float4(acc[i][4], acc[i][5], acc[i][6], acc[i][7]);
    }
    bn_fused_epilogue(acc, tid & 31, ty, o0);
}

// ---------------- GEMM2: g_P[o][m] = sum_c W[o][c] * g_Sa[c][m] -------------
__global__ __launch_bounds__(256) void gemm_proj(const float* __restrict__ W)
{
    __shared__ float As[16][132];
    __shared__ float Bs[16][132];
    int m0 = blockIdx.x * 128;
    int o0 = blockIdx.y * 128;
    int tid = threadIdx.x;
    int tx = tid & 15, ty = tid >> 4;
    int lr = tid >> 2;
    int lk = (tid & 3) << 2;
    int lc = tid >> 5;            // 0..7
    int lm = (tid & 31) << 2;     // 0..124

    float acc[8][8];
#pragma unroll
    for (int i = 0; i < 8; i++)
#pragma unroll
        for (int j = 0; j < 8; j++) acc[i][j] = 0.f;

    for (int k0 = 0; k0 < 512; k0 += 16) {
#pragma unroll
        for (int rr = 0; rr < 2; rr++) {
            int r = lr + rr * 64;
            float4 a = *(const float4*)&W[(size_t)(o0 + r) * 512 + k0 + lk];
            As[lk+0][r] = a.x; As[lk+1][r] = a.y; As[lk+2][r] = a.z; As[lk+3][r] = a.w;
        }
#pragma unroll
        for (int rr = 0; rr < 2; rr++) {
            int c = lc + rr * 8;
            float4 b = *(const float4*)&g_Sa[(size_t)(k0 + c) * MM + m0 + lm];
            *(float4*)&Bs[c][lm] = b;
        }
        __syncthreads();
#pragma unroll
        for (int kk = 0; kk < 16; kk++) {
            float ar[8], br[8];
            *(float4*)&ar[0] = *(const float4*)&As[kk][ty*8];
            *(float4*)&ar[4] = *(const float4*)&As[kk][ty*8+4];
            *(float4*)&br[0] = *(const float4*)&Bs[kk][tx*8];
            *(float4*)&br[4] = *(const float4*)&Bs[kk][tx*8+4];
#pragma unroll
            for (int i = 0; i < 8; i++)
#pragma unroll
                for (int j = 0; j < 8; j++)
                    acc[i][j] = fmaf(ar[i], br[j], acc[i][j]);
        }
        __syncthreads();
    }
#pragma unroll
    for (int i = 0; i < 8; i++) {
        size_t row = (size_t)(o0 + ty*8 + i) * MM + m0 + tx*8;
        *(float4*)&g_P[row]   = make_float4(acc[i][0], acc[i][1], acc[i][2], acc[i][3]);
        *(float4*)&g_P[row+4] = make_float4(acc[i][4], acc[i][5], acc[i][6], acc[i][7]);
    }
    bn_fused_epilogue(acc, tid & 31, ty, 1536 + o0);
}

// -------- BN finalize: fused accumulators -> scale/shift ----------------------
__global__ __launch_bounds__(256) void bn_final(int inbase, int outbase, int which,
    const float* __restrict__ gamma, const float* __restrict__ beta)
{
    int c = blockIdx.x * 256 + threadIdx.x;   // 0..511
    double s  = g_accS [inbase + c];
    double ss = g_accSS[inbase + c];
    double mean = s * (1.0 / (double)MM);
    double var  = ss * (1.0 / (double)MM) - mean * mean;
    double inv  = 1.0 / sqrt(var + 1e-5);
    double g    = (double)gamma[c];
    float* sc = which ? g_scale2 : g_scale;
    float* sf = which ? g_shift2 : g_shift;
    sc[outbase + c] = (float)(g * inv);
    sf[outbase + c] = (float)((double)beta[c] - mean * g * inv);
}

// -------- LIF over T (tau=2 -> *0.5, hard reset), qkv: vth=1.0, float4 --------
__global__ __launch_bounds__(256) void lif_qkv()
{
    int ch = blockIdx.x;            // 0..1535
    int b  = blockIdx.y;            // 0..7
    float sc = g_scale[ch], sf = g_shift[ch];
    int n4 = threadIdx.x * 4;
    float4 v = make_float4(0.f, 0.f, 0.f, 0.f);
#pragma unroll
    for (int t = 0; t < 4; t++) {
        size_t idx = (size_t)ch * MM + (size_t)t * 8192 + b * 1024 + n4;
        float4 y = *(const float4*)&g_Y[idx];
        float4 xv = make_float4(y.x*sc+sf, y.y*sc+sf, y.z*sc+sf, y.w*sc+sf);
        v.x = v.x + (xv.x - v.x)*0.5f; v.y = v.y + (xv.y - v.y)*0.5f;
        v.z = v.z + (xv.z - v.z)*0.5f; v.w = v.w + (xv.w - v.w)*0.5f;
        bool s0 = v.x >= 1.0f, s1 = v.y >= 1.0f, s2 = v.z >= 1.0f, s3 = v.w >= 1.0f;
        *(float4*)&g_S[idx] = make_float4(s0?1.f:0.f, s1?1.f:0.f, s2?1.f:0.f, s3?1.f:0.f);
        if (s0) v.x = 0.f; if (s1) v.y = 0.f; if (s2) v.z = 0.f; if (s3) v.w = 0.f;
    }
}

// -------- attn LIF: vth=0.5, float4 --------
__global__ __launch_bounds__(256) void lif_attn()
{
    int ch = blockIdx.x;            // 0..511
    int b  = blockIdx.y;
    int n4 = threadIdx.x * 4;
    float4 v = make_float4(0.f, 0.f, 0.f, 0.f);
#pragma unroll
    for (int t = 0; t < 4; t++) {
        size_t idx = (size_t)ch * MM + (size_t)t * 8192 + b * 1024 + n4;
        float4 xv = *(const float4*)&g_A[idx];
        v.x = v.x + (xv.x - v.x)*0.5f; v.y = v.y + (xv.y - v.y)*0.5f;
        v.z = v.z + (xv.z - v.z)*0.5f; v.w = v.w + (xv.w - v.w)*0.5f;
        bool s0 = v.x >= 0.5f, s1 = v.y >= 0.5f, s2 = v.z >= 0.5f, s3 = v.w >= 0.5f;
        *(float4*)&g_Sa[idx] = make_float4(s0?1.f:0.f, s1?1.f:0.f, s2?1.f:0.f, s3?1.f:0.f);
        if (s0) v.x = 0.f; if (s1) v.y = 0.f; if (s2) v.z = 0.f; if (s3) v.w = 0.f;
    }
}

// -------- kv[g][d][e] = sum_n K[d][n] * V[e][n] (R14-proven) ------------------
__global__ __launch_bounds__(256) void kv_kernel()
{
    __shared__ float Ks[64][65];
    __shared__ float Vs[64][65];
    int g  = blockIdx.x;            // tb*8 + h
    int tb = g >> 3, h = g & 7;
    int tid = threadIdx.x;
    int tx = tid & 15, ty = tid >> 4;
    size_t kbase = (size_t)(512  + h*64) * MM + (size_t)tb * 1024;
    size_t vbase = (size_t)(1024 + h*64) * MM + (size_t)tb * 1024;
    float acc[4][4];
#pragma unroll
    for (int i = 0; i < 4; i++)
#pragma unroll
        for (int j = 0; j < 4; j++) acc[i][j] = 0.f;

    for (int n0 = 0; n0 < 1024; n0 += 64) {
        for (int i = tid; i < 1024; i += 256) {
            int d = i >> 4, c4 = (i & 15) << 2;
            float4 kk = *(const float4*)&g_S[kbase + (size_t)d * MM + n0 + c4];
            Ks[d][c4+0]=kk.x; Ks[d][c4+1]=kk.y; Ks[d][c4+2]=kk.z; Ks[d][c4+3]=kk.w;
            float4 vv = *(const float4*)&g_S[vbase + (size_t)d * MM + n0 + c4];
            Vs[d][c4+0]=vv.x; Vs[d][c4+1]=vv.y; Vs[d][c4+2]=vv.z; Vs[d][c4+3]=vv.w;
        }
        __syncthreads();
#pragma unroll
        for (int j = 0; j < 64; j++) {
            float kr[4], vr[4];
#pragma unroll
            for (int i = 0; i < 4; i++) kr[i] = Ks[ty*4+i][j];
#pragma unroll
            for (int i = 0; i < 4; i++) vr[i] = Vs[tx*4+i][j];
#pragma unroll
            for (int i = 0; i < 4; i++)
#pragma unroll
                for (int jj = 0; jj < 4; jj++)
                    acc[i][jj] = fmaf(kr[i], vr[jj], acc[i][jj]);
        }
        __syncthreads();
    }
#pragma unroll
    for (int i = 0; i < 4; i++)
#pragma unroll
        for (int j = 0; j < 4; j++)
            g_KV[(size_t)g*4096 + (ty*4+i)*64 + tx*4 + j] = acc[i][j];
}

// -------- a[c=h*64+e][m] = 0.125 * sum_d kv[d][e] * Q[d][n] (R14-proven) ------
__global__ __launch_bounds__(256) void attn_a()
{
    __shared__ float KVs[64][68];
    __shared__ float Qs [64][68];
    int n0 = blockIdx.x * 64;
    int g  = blockIdx.y;
    int tb = g >> 3, h = g & 7;
    int tid = threadIdx.x;
    int tx = tid & 15, ty = tid >> 4;
    size_t qbase = (size_t)(h*64) * MM + (size_t)tb * 1024 + n0;
    for (int i = tid; i < 1024; i += 256) {
        int d = i >> 4, c4 = (i & 15) << 2;
        *(float4*)&KVs[d][c4] = *(const float4*)&g_KV[(size_t)g*4096 + d*64 + c4];
        *(float4*)&Qs[d][c4]  = *(const float4*)&g_S[qbase + (size_t)d * MM + c4];
    }
    __syncthreads();
    float acc[4][4];
#pragma unroll
    for (int i = 0; i < 4; i++)
#pragma unroll
        for (int j = 0; j < 4; j++) acc[i][j] = 0.f;
#pragma unroll
    for (int d = 0; d < 64; d++) {
        float4 kv4 = *(const float4*)&KVs[d][ty*4];
        float4 q4  = *(const float4*)&Qs[d][tx*4];
        float kvv[4] = {kv4.x, kv4.y, kv4.z, kv4.w};
        float qv[4]  = {q4.x,  q4.y,  q4.z,  q4.w};
#pragma unroll
        for (int i = 0; i < 4; i++)
#pragma unroll
            for (int j = 0; j < 4; j++)
                acc[i][j] = fmaf(kvv[i], qv[j], acc[i][j]);
    }
#pragma unroll
    for (int i = 0; i < 4; i++) {
        int e = ty*4 + i;
        size_t base = (size_t)(h*64 + e) * MM + (size_t)tb * 1024 + n0 + tx*4;
        *(float4*)&g_A[base] = make_float4(0.125f*acc[i][0], 0.125f*acc[i][1],
                                           0.125f*acc[i][2], 0.125f*acc[i][3]);
    }
}

// -------- final LIF (vth=1.0, float4) + transpose (R15-proven bit-exact) ------
__global__ __launch_bounds__(256) void lif_final(float* __restrict__ out)
{
    int c = blockIdx.x;
    int b = blockIdx.y;
    float sc = g_scale2[c], sf = g_shift2[c];
    int n4 = threadIdx.x * 4;
    float4 v = make_float4(0.f, 0.f, 0.f, 0.f);
#pragma unroll
    for (int t = 0; t < 4; t++) {
        float4 y = *(const float4*)&g_P[(size_t)c * MM + (size_t)(t*8 + b) * 1024 + n4];
        float4 xv = make_float4(y.x*sc+sf, y.y*sc+sf, y.z*sc+sf, y.w*sc+sf);
        v.x = v.x + (xv.x - v.x)*0.5f; v.y = v.y + (xv.y - v.y)*0.5f;
        v.z = v.z + (xv.z - v.z)*0.5f; v.w = v.w + (xv.w - v.w)*0.5f;
        bool s0 = v.x >= 1.0f, s1 = v.y >= 1.0f, s2 = v.z >= 1.0f, s3 = v.w >= 1.0f;
        *(float4*)&out[((size_t)(t*8 + b) * 512 + c) * 1024 + n4] =
            make_float4(s0?1.f:0.f, s1?1.f:0.f, s2?1.f:0.f, s3?1.f:0.f);
        if (s0) v.x = 0.f; if (s1) v.y = 0.f; if (s2) v.z = 0.f; if (s3) v.w = 0.f;
    }
}

// ---------------------------------------------------------------------------
extern "C" void kernel_launch(void* const* d_in, const int* in_sizes, int n_in,
                              void* d_out, int out_size)
{
    const float* x   = (const float*)d_in[0];
    const float* q_w = (const float*)d_in[1];
    const float* q_g = (const float*)d_in[2];
    const float* q_b = (const float*)d_in[3];
    const float* k_w = (const float*)d_in[4];
    const float* k_g = (const float*)d_in[5];
    const float* k_b = (const float*)d_in[6];
    const float* v_w = (const float*)d_in[7];
    const float* v_g = (const float*)d_in[8];
    const float* v_b = (const float*)d_in[9];
    const float* p_w = (const float*)d_in[10];
    // d_in[11] = proj_b: added before training-mode BN -> cancels exactly.
    const float* p_g = (const float*)d_in[12];
    const float* p_b = (const float*)d_in[13];
    float* out = (float*)d_out;

    // 0) zero fused BN accumulators
    zero_acc<<<1, 256>>>();
    // 1) fused QKV GEMM (bit-exact) + fused BN stats
    gemm_qkv<<<dim3(MM/128, O3/128), 256>>>(q_w, k_w, v_w, x);
    // 2) BN finalize (reads fused accumulators directly)
    bn_final<<<2, 256>>>(0,    0,    0, q_g, q_b);
    bn_final<<<2, 256>>>(512,  512,  0, k_g, k_b);
    bn_final<<<2, 256>>>(1024, 1024, 0, v_g, v_b);
    // 3) LIF -> binary spikes (vth=1.0, float4)
    lif_qkv<<<dim3(O3, 8), 256>>>();
    // 4) kv = K^T V per (t,b,h) (exact integers)
    kv_kernel<<<256, 256>>>();
    // 5) a = Q kv * 0.125 (exact)
    attn_a<<<dim3(16, 256), 256>>>();
    // 6) attn LIF (vth=0.5, float4)
    lif_attn<<<dim3(CC, 8), 256>>>();
    // 7) proj GEMM (bit-exact) + fused BN stats
    gemm_proj<<<dim3(MM/128, CC/128), 256>>>(p_w);
    // 8) proj BN finalize
    bn_final<<<2, 256>>>(1536, 0, 1, p_g, p_b);
    // 9) final LIF (float4) + transpose to [T,B,C,H,W]
    lif_final<<<dim3(CC, 8), 256>>>(out);
}

// round 17
// speedup vs baseline: 1.2101x; 1.0084x over previous
#include <cuda_runtime.h>
#include <math.h>
#include <stdint.h>

// Problem constants: T=4, B=8, N=1024, C=512, NH=8, D=64, TB=32, M=TB*N=32768
#define MM 32768
#define O3 1536
#define CC 512

// ---------------- scratch (static __device__, no allocation) ----------------
__device__ float g_Y [(size_t)O3 * MM];   // qkv pre-activations   [o][m]
__device__ float g_S [(size_t)O3 * MM];   // qkv spikes            [o][m]
__device__ float g_KV[256 * 64 * 64];     // kv per (t,b,h)        [g][d][e]
__device__ float g_Sa[(size_t)CC * MM];   // attention spikes      [c][m]
__device__ float g_P [(size_t)CC * MM];   // proj pre-activations  [c][m]
__device__ float g_scale [O3], g_shift [O3];
__device__ float g_scale2[CC], g_shift2[CC];
__device__ double g_accS [2048];          // fused BN sums   (qkv 0..1535, proj 1536..2047)
__device__ double g_accSS[2048];          // fused BN sumsqs

__global__ void zero_acc()
{
    for (int i = threadIdx.x; i < 2048; i += 256) { g_accS[i] = 0.0; g_accSS[i] = 0.0; }
}

// -------- fused BN-partial epilogue helper (R16-proven) -----------------------
__device__ __forceinline__ void bn_fused_epilogue(
    float acc[8][8], int lane, int ty, int obase)
{
#pragma unroll
    for (int i = 0; i < 8; i++) {
        float s = 0.f, ss = 0.f;
#pragma unroll
        for (int j = 0; j < 8; j++) {
            s += acc[i][j];
            ss = fmaf(acc[i][j], acc[i][j], ss);
        }
#pragma unroll
        for (int off = 8; off > 0; off >>= 1) {
            s  += __shfl_down_sync(0xffffffffu, s,  off, 16);
            ss += __shfl_down_sync(0xffffffffu, ss, off, 16);
        }
        if ((lane & 15) == 0) {
            atomicAdd(&g_accS [obase + ty * 8 + i], (double)s);
            atomicAdd(&g_accSS[obase + ty * 8 + i], (double)ss);
        }
    }
}

// ---------------- GEMM1 (R16-proven: bit-exact + fused BN stats) -------------
__global__ __launch_bounds__(256) void gemm_qkv(
    const float* __restrict__ Wq, const float* __restrict__ Wk,
    const float* __restrict__ Wv, const float* __restrict__ X)
{
    __shared__ float As[16][132];
    __shared__ float Bs[16][132];
    int m0 = blockIdx.x * 128;
    int o0 = blockIdx.y * 128;
    const float* W = Wq; int ob = o0;
    if (o0 >= 1024)      { W = Wv; ob = o0 - 1024; }
    else if (o0 >= 512)  { W = Wk; ob = o0 - 512;  }

    int tid = threadIdx.x;
    int tx = tid & 15, ty = tid >> 4;
    int lr = tid >> 2;
    int lk = (tid & 3) << 2;

    float acc[8][8];
#pragma unroll
    for (int i = 0; i < 8; i++)
#pragma unroll
        for (int j = 0; j < 8; j++) acc[i][j] = 0.f;

    for (int k0 = 0; k0 < 512; k0 += 16) {
#pragma unroll
        for (int rr = 0; rr < 2; rr++) {
            int r = lr + rr * 64;
            float4 a = *(const float4*)&W[(size_t)(ob + r) * 512 + k0 + lk];
            As[lk+0][r] = a.x; As[lk+1][r] = a.y; As[lk+2][r] = a.z; As[lk+3][r] = a.w;
            float4 b = *(const float4*)&X[(size_t)(m0 + r) * 512 + k0 + lk];
            Bs[lk+0][r] = b.x; Bs[lk+1][r] = b.y; Bs[lk+2][r] = b.z; Bs[lk+3][r] = b.w;
        }
        __syncthreads();
#pragma unroll
        for (int kk = 0; kk < 16; kk++) {
            float ar[8], br[8];
            *(float4*)&ar[0] = *(const float4*)&As[kk][ty*8];
            *(float4*)&ar[4] = *(const float4*)&As[kk][ty*8+4];
            *(float4*)&br[0] = *(const float4*)&Bs[kk][tx*8];
            *(float4*)&br[4] = *(const float4*)&Bs[kk][tx*8+4];
#pragma unroll
            for (int i = 0; i < 8; i++)
#pragma unroll
                for (int j = 0; j < 8; j++)
                    acc[i][j] = fmaf(ar[i], br[j], acc[i][j]);
        }
        __syncthreads();
    }
#pragma unroll
    for (int i = 0; i < 8; i++) {
        size_t row = (size_t)(o0 + ty*8 + i) * MM + m0 + tx*8;
        *(float4*)&g_Y[row]   = make_float4(acc[i][0], acc[i][1], acc[i][2], acc[i][3]);
        *(float4*)&g_Y[row+4] = make_float4(acc[i][4], acc[i][5], acc[i][6], acc[i][7]);
    }
    bn_fused_epilogue(acc, tid & 31, ty, o0);
}

// ---------------- GEMM2 (R16-proven) -----------------------------------------
__global__ __launch_bounds__(256) void gemm_proj(const float* __restrict__ W)
{
    __shared__ float As[16][132];
    __shared__ float Bs[16][132];
    int m0 = blockIdx.x * 128;
    int o0 = blockIdx.y * 128;
    int tid = threadIdx.x;
    int tx = tid & 15, ty = tid >> 4;
    int lr = tid >> 2;
    int lk = (tid & 3) << 2;
    int lc = tid >> 5;
    int lm = (tid & 31) << 2;

    float acc[8][8];
#pragma unroll
    for (int i = 0; i < 8; i++)
#pragma unroll
        for (int j = 0; j < 8; j++) acc[i][j] = 0.f;

    for (int k0 = 0; k0 < 512; k0 += 16) {
#pragma unroll
        for (int rr = 0; rr < 2; rr++) {
            int r = lr + rr * 64;
            float4 a = *(const float4*)&W[(size_t)(o0 + r) * 512 + k0 + lk];
            As[lk+0][r] = a.x; As[lk+1][r] = a.y; As[lk+2][r] = a.z; As[lk+3][r] = a.w;
        }
#pragma unroll
        for (int rr = 0; rr < 2; rr++) {
            int c = lc + rr * 8;
            float4 b = *(const float4*)&g_Sa[(size_t)(k0 + c) * MM + m0 + lm];
            *(float4*)&Bs[c][lm] = b;
        }
        __syncthreads();
#pragma unroll
        for (int kk = 0; kk < 16; kk++) {
            float ar[8], br[8];
            *(float4*)&ar[0] = *(const float4*)&As[kk][ty*8];
            *(float4*)&ar[4] = *(const float4*)&As[kk][ty*8+4];
            *(float4*)&br[0] = *(const float4*)&Bs[kk][tx*8];
            *(float4*)&br[4] = *(const float4*)&Bs[kk][tx*8+4];
#pragma unroll
            for (int i = 0; i < 8; i++)
#pragma unroll
                for (int j = 0; j < 8; j++)
                    acc[i][j] = fmaf(ar[i], br[j], acc[i][j]);
        }
        __syncthreads();
    }
#pragma unroll
    for (int i = 0; i < 8; i++) {
        size_t row = (size_t)(o0 + ty*8 + i) * MM + m0 + tx*8;
        *(float4*)&g_P[row]   = make_float4(acc[i][0], acc[i][1], acc[i][2], acc[i][3]);
        *(float4*)&g_P[row+4] = make_float4(acc[i][4], acc[i][5], acc[i][6], acc[i][7]);
    }
    bn_fused_epilogue(acc, tid & 31, ty, 1536 + o0);
}

// -------- BN finalize: all 1536 qkv channels in ONE launch --------------------
__global__ __launch_bounds__(256) void bn_final_qkv(
    const float* __restrict__ q_g, const float* __restrict__ q_b,
    const float* __restrict__ k_g, const float* __restrict__ k_b,
    const float* __restrict__ v_g, const float* __restrict__ v_b)
{
    int c = blockIdx.x * 256 + threadIdx.x;   // 0..1535
    const float* gam; const float* bet; int cl;
    if (c < 512)       { gam = q_g; bet = q_b; cl = c; }
    else if (c < 1024) { gam = k_g; bet = k_b; cl = c - 512; }
    else               { gam = v_g; bet = v_b; cl = c - 1024; }
    double s  = g_accS [c];
    double ss = g_accSS[c];
    double mean = s * (1.0 / (double)MM);
    double var  = ss * (1.0 / (double)MM) - mean * mean;
    double inv  = 1.0 / sqrt(var + 1e-5);
    double g    = (double)gam[cl];
    g_scale[c] = (float)(g * inv);
    g_shift[c] = (float)((double)bet[cl] - mean * g * inv);
}

__global__ __launch_bounds__(256) void bn_final_proj(
    const float* __restrict__ gamma, const float* __restrict__ beta)
{
    int c = blockIdx.x * 256 + threadIdx.x;   // 0..511
    double s  = g_accS [1536 + c];
    double ss = g_accSS[1536 + c];
    double mean = s * (1.0 / (double)MM);
    double var  = ss * (1.0 / (double)MM) - mean * mean;
    double inv  = 1.0 / sqrt(var + 1e-5);
    double g    = (double)gamma[c];
    g_scale2[c] = (float)(g * inv);
    g_shift2[c] = (float)((double)beta[c] - mean * g * inv);
}

// -------- LIF qkv (vth=1.0, float4, R16-proven) --------------------------------
__global__ __launch_bounds__(256) void lif_qkv()
{
    int ch = blockIdx.x;
    int b  = blockIdx.y;
    float sc = g_scale[ch], sf = g_shift[ch];
    int n4 = threadIdx.x * 4;
    float4 v = make_float4(0.f, 0.f, 0.f, 0.f);
#pragma unroll
    for (int t = 0; t < 4; t++) {
        size_t idx = (size_t)ch * MM + (size_t)t * 8192 + b * 1024 + n4;
        float4 y = *(const float4*)&g_Y[idx];
        float4 xv = make_float4(y.x*sc+sf, y.y*sc+sf, y.z*sc+sf, y.w*sc+sf);
        v.x = v.x + (xv.x - v.x)*0.5f; v.y = v.y + (xv.y - v.y)*0.5f;
        v.z = v.z + (xv.z - v.z)*0.5f; v.w = v.w + (xv.w - v.w)*0.5f;
        bool s0 = v.x >= 1.0f, s1 = v.y >= 1.0f, s2 = v.z >= 1.0f, s3 = v.w >= 1.0f;
        *(float4*)&g_S[idx] = make_float4(s0?1.f:0.f, s1?1.f:0.f, s2?1.f:0.f, s3?1.f:0.f);
        if (s0) v.x = 0.f; if (s1) v.y = 0.f; if (s2) v.z = 0.f; if (s3) v.w = 0.f;
    }
}

// -------- kv[g][d][e] = sum_n K[d][n] * V[e][n] (R14/R16-proven) ---------------
__global__ __launch_bounds__(256) void kv_kernel()
{
    __shared__ float Ks[64][65];
    __shared__ float Vs[64][65];
    int g  = blockIdx.x;
    int tb = g >> 3, h = g & 7;
    int tid = threadIdx.x;
    int tx = tid & 15, ty = tid >> 4;
    size_t kbase = (size_t)(512  + h*64) * MM + (size_t)tb * 1024;
    size_t vbase = (size_t)(1024 + h*64) * MM + (size_t)tb * 1024;
    float acc[4][4];
#pragma unroll
    for (int i = 0; i < 4; i++)
#pragma unroll
        for (int j = 0; j < 4; j++) acc[i][j] = 0.f;

    for (int n0 = 0; n0 < 1024; n0 += 64) {
        for (int i = tid; i < 1024; i += 256) {
            int d = i >> 4, c4 = (i & 15) << 2;
            float4 kk = *(const float4*)&g_S[kbase + (size_t)d * MM + n0 + c4];
            Ks[d][c4+0]=kk.x; Ks[d][c4+1]=kk.y; Ks[d][c4+2]=kk.z; Ks[d][c4+3]=kk.w;
            float4 vv = *(const float4*)&g_S[vbase + (size_t)d * MM + n0 + c4];
            Vs[d][c4+0]=vv.x; Vs[d][c4+1]=vv.y; Vs[d][c4+2]=vv.z; Vs[d][c4+3]=vv.w;
        }
        __syncthreads();
#pragma unroll
        for (int j = 0; j < 64; j++) {
            float kr[4], vr[4];
#pragma unroll
            for (int i = 0; i < 4; i++) kr[i] = Ks[ty*4+i][j];
#pragma unroll
            for (int i = 0; i < 4; i++) vr[i] = Vs[tx*4+i][j];
#pragma unroll
            for (int i = 0; i < 4; i++)
#pragma unroll
                for (int jj = 0; jj < 4; jj++)
                    acc[i][jj] = fmaf(kr[i], vr[jj], acc[i][jj]);
        }
        __syncthreads();
    }
#pragma unroll
    for (int i = 0; i < 4; i++)
#pragma unroll
        for (int j = 0; j < 4; j++)
            g_KV[(size_t)g*4096 + (ty*4+i)*64 + tx*4 + j] = acc[i][j];
}

// -------- FUSED attn: a = Q·kv * 0.125 then attn-LIF (vth=0.5) -> g_Sa --------
// Grid: (n-tile 0..15, b*8+h 0..63). t looped inside; membrane in registers.
// Arithmetic identical to attn_a + lif_attn (store/load of g_A elided, exact).
__global__ __launch_bounds__(256) void attn_fused()
{
    __shared__ float KVs[64][68];
    __shared__ float Qs [64][68];
    int n0 = blockIdx.x * 64;
    int bh = blockIdx.y;
    int b = bh >> 3, h = bh & 7;
    int tid = threadIdx.x;
    int tx = tid & 15, ty = tid >> 4;

    float v[4][4];
#pragma unroll
    for (int i = 0; i < 4; i++)
#pragma unroll
        for (int j = 0; j < 4; j++) v[i][j] = 0.f;

#pragma unroll 1
    for (int t = 0; t < 4; t++) {
        int tb = t * 8 + b;
        int g = tb * 8 + h;
        size_t qbase = (size_t)(h*64) * MM + (size_t)tb * 1024 + n0;
        __syncthreads();
        for (int i = tid; i < 1024; i += 256) {
            int d = i >> 4, c4 = (i & 15) << 2;
            *(float4*)&KVs[d][c4] = *(const float4*)&g_KV[(size_t)g*4096 + d*64 + c4];
            *(float4*)&Qs[d][c4]  = *(const float4*)&g_S[qbase + (size_t)d * MM + c4];
        }
        __syncthreads();
        float acc[4][4];
#pragma unroll
        for (int i = 0; i < 4; i++)
#pragma unroll
            for (int j = 0; j < 4; j++) acc[i][j] = 0.f;
#pragma unroll
        for (int d = 0; d < 64; d++) {
            float4 kv4 = *(const float4*)&KVs[d][ty*4];
            float4 q4  = *(const float4*)&Qs[d][tx*4];
            float kvv[4] = {kv4.x, kv4.y, kv4.z, kv4.w};
            float qv[4]  = {q4.x,  q4.y,  q4.z,  q4.w};
#pragma unroll
            for (int i = 0; i < 4; i++)
#pragma unroll
                for (int j = 0; j < 4; j++)
                    acc[i][j] = fmaf(kvv[i], qv[j], acc[i][j]);
        }
        // LIF step for this t (xv identical to attn_a's stored value)
#pragma unroll
        for (int i = 0; i < 4; i++) {
            int e = ty*4 + i;
            float4 sp;
            float xv0 = 0.125f*acc[i][0];
            float xv1 = 0.125f*acc[i][1];
            float xv2 = 0.125f*acc[i][2];
            float xv3 = 0.125f*acc[i][3];
            v[i][0] = v[i][0] + (xv0 - v[i][0])*0.5f;
            v[i][1] = v[i][1] + (xv1 - v[i][1])*0.5f;
            v[i][2] = v[i][2] + (xv2 - v[i][2])*0.5f;
            v[i][3] = v[i][3] + (xv3 - v[i][3])*0.5f;
            bool s0 = v[i][0] >= 0.5f, s1 = v[i][1] >= 0.5f;
            bool s2 = v[i][2] >= 0.5f, s3 = v[i][3] >= 0.5f;
            sp = make_float4(s0?1.f:0.f, s1?1.f:0.f, s2?1.f:0.f, s3?1.f:0.f);
            *(float4*)&g_Sa[(size_t)(h*64 + e) * MM + (size_t)tb * 1024 + n0 + tx*4] = sp;
            if (s0) v[i][0] = 0.f; if (s1) v[i][1] = 0.f;
            if (s2) v[i][2] = 0.f; if (s3) v[i][3] = 0.f;
        }
    }
}

// -------- final LIF (vth=1.0, float4) + transpose (R16-proven) -----------------
__global__ __launch_bounds__(256) void lif_final(float* __restrict__ out)
{
    int c = blockIdx.x;
    int b = blockIdx.y;
    float sc = g_scale2[c], sf = g_shift2[c];
    int n4 = threadIdx.x * 4;
    float4 v = make_float4(0.f, 0.f, 0.f, 0.f);
#pragma unroll
    for (int t = 0; t < 4; t++) {
        float4 y = *(const float4*)&g_P[(size_t)c * MM + (size_t)(t*8 + b) * 1024 + n4];
        float4 xv = make_float4(y.x*sc+sf, y.y*sc+sf, y.z*sc+sf, y.w*sc+sf);
        v.x = v.x + (xv.x - v.x)*0.5f; v.y = v.y + (xv.y - v.y)*0.5f;
        v.z = v.z + (xv.z - v.z)*0.5f; v.w = v.w + (xv.w - v.w)*0.5f;
        bool s0 = v.x >= 1.0f, s1 = v.y >= 1.0f, s2 = v.z >= 1.0f, s3 = v.w >= 1.0f;
        *(float4*)&out[((size_t)(t*8 + b) * 512 + c) * 1024 + n4] =
            make_float4(s0?1.f:0.f, s1?1.f:0.f, s2?1.f:0.f, s3?1.f:0.f);
        if (s0) v.x = 0.f; if (s1) v.y = 0.f; if (s2) v.z = 0.f; if (s3) v.w = 0.f;
    }
}

// ---------------------------------------------------------------------------
extern "C" void kernel_launch(void* const* d_in, const int* in_sizes, int n_in,
                              void* d_out, int out_size)
{
    const float* x   = (const float*)d_in[0];
    const float* q_w = (const float*)d_in[1];
    const float* q_g = (const float*)d_in[2];
    const float* q_b = (const float*)d_in[3];
    const float* k_w = (const float*)d_in[4];
    const float* k_g = (const float*)d_in[5];
    const float* k_b = (const float*)d_in[6];
    const float* v_w = (const float*)d_in[7];
    const float* v_g = (const float*)d_in[8];
    const float* v_b = (const float*)d_in[9];
    const float* p_w = (const float*)d_in[10];
    // d_in[11] = proj_b: added before training-mode BN -> cancels exactly.
    const float* p_g = (const float*)d_in[12];
    const float* p_b = (const float*)d_in[13];
    float* out = (float*)d_out;

    // 0) zero fused BN accumulators
    zero_acc<<<1, 256>>>();
    // 1) fused QKV GEMM (bit-exact) + fused BN stats
    gemm_qkv<<<dim3(MM/128, O3/128), 256>>>(q_w, k_w, v_w, x);
    // 2) BN finalize (single launch for all 1536 channels)
    bn_final_qkv<<<6, 256>>>(q_g, q_b, k_g, k_b, v_g, v_b);
    // 3) LIF -> binary spikes (vth=1.0, float4)
    lif_qkv<<<dim3(O3, 8), 256>>>();
    // 4) kv = K^T V per (t,b,h) (exact integers)
    kv_kernel<<<256, 256>>>();
    // 5+6) a = Q kv * 0.125 + attn LIF fused (exact, g_A eliminated)
    attn_fused<<<dim3(16, 64), 256>>>();
    // 7) proj GEMM (bit-exact) + fused BN stats
    gemm_proj<<<dim3(MM/128, CC/128), 256>>>(p_w);
    // 8) proj BN finalize
    bn_final_proj<<<2, 256>>>(p_g, p_b);
    // 9) final LIF (float4) + transpose to [T,B,C,H,W]
    lif_final<<<dim3(CC, 8), 256>>>(out);
}